// round 1
// baseline (speedup 1.0000x reference)
#include <cuda_runtime.h>
#include <cuda_bf16.h>
#include <math.h>

// ---------------------------------------------------------------------------
// Problem constants
// ---------------------------------------------------------------------------
#define BB   2
#define SS   1024
#define DD   1024
#define HH   16
#define DKV  64
#define DHH  4096
#define LL   8
#define VV   256
#define MM   (BB*SS)          // 2048 rows

// ---------------------------------------------------------------------------
// Scratch (device globals: allocation-free)
// ---------------------------------------------------------------------------
__device__ float g_x [MM*DD];
__device__ float g_q [MM*DD];
__device__ float g_k [MM*DD];
__device__ float g_v [MM*DD];
__device__ float g_o [MM*DD];
__device__ float g_h [MM*DD];
__device__ float g_t [MM*DHH];

// ---------------------------------------------------------------------------
// Embedding: x[b,s,:] = emb[tokens[b,s],:] + pos[s,:]
// ---------------------------------------------------------------------------
__global__ void embed_kernel(const int* __restrict__ tokens,
                             const float* __restrict__ emb,
                             const float* __restrict__ pos,
                             float* __restrict__ x)
{
    int i = blockIdx.x;            // 0..2047 (b*S+s)
    int s = i & (SS - 1);
    int t = tokens[i];
    const float4* e4 = (const float4*)(emb + (size_t)t * DD);
    const float4* p4 = (const float4*)(pos + (size_t)s * DD);
    float4*       x4 = (float4*)(x + (size_t)i * DD);
    int d = threadIdx.x;           // 256 threads, DD/4 = 256 float4s
    float4 a = e4[d], b = p4[d];
    x4[d] = make_float4(a.x + b.x, a.y + b.y, a.z + b.z, a.w + b.w);
}

// ---------------------------------------------------------------------------
// SGEMM: C[M,N] = act( A[M,K] @ W[K,N] + bias ) + res
//   BM=BN=128, BK=8, 256 threads, 8x8 per thread, double-buffered smem.
//   M % 128 == 0, N % 128 == 0, K % 8 == 0 (all true for this problem).
//   gelu: exact erf-based GELU applied to (A@W + bias) BEFORE residual add.
// ---------------------------------------------------------------------------
__device__ __forceinline__ float gelu_exact(float v)
{
    return 0.5f * v * (1.0f + erff(v * 0.70710678118654752f));
}

__global__ void __launch_bounds__(256, 2)
sgemm_kernel(const float* __restrict__ A, const float* __restrict__ W,
             const float* __restrict__ bias, const float* __restrict__ res,
             float* __restrict__ C, int M, int N, int K, int gelu)
{
    __shared__ float As[2][8][128];
    __shared__ float Bs[2][8][128];

    const int tid  = threadIdx.x;
    const int m0   = blockIdx.y * 128;
    const int n0   = blockIdx.x * 128;

    // load indices
    const int aRow = tid >> 1;            // 0..127
    const int aCol = (tid & 1) * 4;       // 0 or 4
    const int bRow = tid >> 5;            // 0..7
    const int bCol = (tid & 31) * 4;      // 0..124

    // compute indices
    const int tr = tid >> 4;              // 0..15 -> rows tr*8..tr*8+7
    const int tc = tid & 15;              // 0..15 -> cols tc*8..tc*8+7

    float acc[8][8];
#pragma unroll
    for (int i = 0; i < 8; i++)
#pragma unroll
        for (int j = 0; j < 8; j++) acc[i][j] = 0.0f;

    const float* Aptr = A + (size_t)(m0 + aRow) * K + aCol;
    const float* Wptr = W + (size_t)bRow * N + n0 + bCol;

    // --- preload tile 0 ---
    {
        float4 a4 = *(const float4*)Aptr;
        As[0][aCol + 0][aRow] = a4.x;
        As[0][aCol + 1][aRow] = a4.y;
        As[0][aCol + 2][aRow] = a4.z;
        As[0][aCol + 3][aRow] = a4.w;
        *(float4*)&Bs[0][bRow][bCol] = *(const float4*)Wptr;
    }
    __syncthreads();

    const int nt = K >> 3;
    for (int t = 0; t < nt; t++) {
        const int buf = t & 1;
        float4 na, nb;
        if (t + 1 < nt) {
            na = *(const float4*)(Aptr + (size_t)(t + 1) * 8);
            nb = *(const float4*)(Wptr + (size_t)(t + 1) * 8 * N);
        }
#pragma unroll
        for (int kk = 0; kk < 8; kk++) {
            float ra[8], rb[8];
            *(float4*)(ra)     = *(const float4*)&As[buf][kk][tr * 8];
            *(float4*)(ra + 4) = *(const float4*)&As[buf][kk][tr * 8 + 4];
            *(float4*)(rb)     = *(const float4*)&Bs[buf][kk][tc * 8];
            *(float4*)(rb + 4) = *(const float4*)&Bs[buf][kk][tc * 8 + 4];
#pragma unroll
            for (int i = 0; i < 8; i++)
#pragma unroll
                for (int j = 0; j < 8; j++)
                    acc[i][j] += ra[i] * rb[j];
        }
        if (t + 1 < nt) {
            const int nbuf = buf ^ 1;
            As[nbuf][aCol + 0][aRow] = na.x;
            As[nbuf][aCol + 1][aRow] = na.y;
            As[nbuf][aCol + 2][aRow] = na.z;
            As[nbuf][aCol + 3][aRow] = na.w;
            *(float4*)&Bs[nbuf][bRow][bCol] = nb;
        }
        __syncthreads();
    }

    // --- epilogue ---
    float bv[8];
#pragma unroll
    for (int j = 0; j < 8; j++)
        bv[j] = bias ? bias[n0 + tc * 8 + j] : 0.0f;

#pragma unroll
    for (int i = 0; i < 8; i++) {
        const int row = m0 + tr * 8 + i;
        float* crow = C + (size_t)row * N + n0 + tc * 8;
        const float* rrow = res ? (res + (size_t)row * N + n0 + tc * 8) : nullptr;
        float v[8];
#pragma unroll
        for (int j = 0; j < 8; j++) {
            float val = acc[i][j] + bv[j];
            if (gelu) val = gelu_exact(val);
            if (rrow) val += rrow[j];
            v[j] = val;
        }
        *(float4*)(crow)     = *(float4*)(v);
        *(float4*)(crow + 4) = *(float4*)(v + 4);
    }
}

// ---------------------------------------------------------------------------
// Flash attention (causal): per (b,h), 64-query tiles, 64-key tiles, DK=DV=64.
// q,k,v layout: [B*S, H*64] row-major (column h*64+d).
// ---------------------------------------------------------------------------
#define APAD 65
__global__ void __launch_bounds__(256)
attention_kernel(const float* __restrict__ q, const float* __restrict__ k,
                 const float* __restrict__ v, float* __restrict__ o)
{
    extern __shared__ float sm[];
    float* Qs = sm;                 // 64 x APAD
    float* Ks = Qs + 64 * APAD;
    float* Vs = Ks + 64 * APAD;
    float* Ps = Vs + 64 * APAD;

    const int tid = threadIdx.x;
    const int qb  = blockIdx.x;          // query tile: rows qb*64..+63
    const int bh  = blockIdx.y;          // 0..31
    const int b   = bh >> 4;
    const int h   = bh & 15;
    const size_t rowbase = (size_t)b * SS;     // row index offset into [B*S, ...]
    const int    cbase   = h * DKV;            // column offset

    const int ty = tid >> 4;             // 0..15, owns query rows ty*4..+3
    const int tx = tid & 15;             // 0..15, owns cols tx*4..+3
    const float scale = 0.125f;          // 1/sqrt(64)

    // load Q tile
    for (int it = tid; it < 64 * 16; it += 256) {
        int rr = it >> 4, c4 = (it & 15) * 4;
        float4 a = *(const float4*)(q + (rowbase + qb * 64 + rr) * DD + cbase + c4);
        Qs[rr * APAD + c4 + 0] = a.x;
        Qs[rr * APAD + c4 + 1] = a.y;
        Qs[rr * APAD + c4 + 2] = a.z;
        Qs[rr * APAD + c4 + 3] = a.w;
    }

    float m[4], l[4], acc[4][4];
#pragma unroll
    for (int i = 0; i < 4; i++) {
        m[i] = -INFINITY; l[i] = 0.0f;
#pragma unroll
        for (int j = 0; j < 4; j++) acc[i][j] = 0.0f;
    }
    __syncthreads();

    for (int jt = 0; jt <= qb; jt++) {
        // load K,V tiles (keys jt*64..+63)
        for (int it = tid; it < 64 * 16; it += 256) {
            int rr = it >> 4, c4 = (it & 15) * 4;
            const size_t grow = (rowbase + jt * 64 + rr) * DD + cbase + c4;
            float4 a = *(const float4*)(k + grow);
            Ks[rr * APAD + c4 + 0] = a.x;
            Ks[rr * APAD + c4 + 1] = a.y;
            Ks[rr * APAD + c4 + 2] = a.z;
            Ks[rr * APAD + c4 + 3] = a.w;
            float4 c = *(const float4*)(v + grow);
            Vs[rr * APAD + c4 + 0] = c.x;
            Vs[rr * APAD + c4 + 1] = c.y;
            Vs[rr * APAD + c4 + 2] = c.z;
            Vs[rr * APAD + c4 + 3] = c.w;
        }
        __syncthreads();

        // scores: s[i][j] = Q[ty*4+i] . K[tx*4+j]
        float s[4][4];
#pragma unroll
        for (int i = 0; i < 4; i++)
#pragma unroll
            for (int j = 0; j < 4; j++) s[i][j] = 0.0f;
#pragma unroll 8
        for (int kk = 0; kk < 64; kk++) {
            float qv[4], kv[4];
#pragma unroll
            for (int i = 0; i < 4; i++) qv[i] = Qs[(ty * 4 + i) * APAD + kk];
#pragma unroll
            for (int j = 0; j < 4; j++) kv[j] = Ks[(tx * 4 + j) * APAD + kk];
#pragma unroll
            for (int i = 0; i < 4; i++)
#pragma unroll
                for (int j = 0; j < 4; j++) s[i][j] += qv[i] * kv[j];
        }

        // scale + causal mask
#pragma unroll
        for (int i = 0; i < 4; i++) {
            int qrow = qb * 64 + ty * 4 + i;
#pragma unroll
            for (int j = 0; j < 4; j++) {
                int kcol = jt * 64 + tx * 4 + j;
                s[i][j] = (kcol > qrow) ? -INFINITY : s[i][j] * scale;
            }
        }

        // online softmax update per query row (reduce across 16 lanes of tx)
#pragma unroll
        for (int i = 0; i < 4; i++) {
            float rm = fmaxf(fmaxf(s[i][0], s[i][1]), fmaxf(s[i][2], s[i][3]));
#pragma unroll
            for (int off = 1; off < 16; off <<= 1)
                rm = fmaxf(rm, __shfl_xor_sync(0xffffffffu, rm, off));
            float mnew = fmaxf(m[i], rm);
            float corr = expf(m[i] - mnew);
            l[i] *= corr;
#pragma unroll
            for (int j = 0; j < 4; j++) acc[i][j] *= corr;
            float rs = 0.0f;
#pragma unroll
            for (int j = 0; j < 4; j++) {
                float p = expf(s[i][j] - mnew);
                s[i][j] = p;
                rs += p;
            }
#pragma unroll
            for (int off = 1; off < 16; off <<= 1)
                rs += __shfl_xor_sync(0xffffffffu, rs, off);
            l[i] += rs;
            m[i] = mnew;
        }

        // stash P to smem for the cross-thread PV product
#pragma unroll
        for (int i = 0; i < 4; i++)
#pragma unroll
            for (int j = 0; j < 4; j++)
                Ps[(ty * 4 + i) * APAD + tx * 4 + j] = s[i][j];
        __syncthreads();

        // acc += P @ V
#pragma unroll 8
        for (int kk = 0; kk < 64; kk++) {
            float pv[4], vv[4];
#pragma unroll
            for (int i = 0; i < 4; i++) pv[i] = Ps[(ty * 4 + i) * APAD + kk];
#pragma unroll
            for (int j = 0; j < 4; j++) vv[j] = Vs[kk * APAD + tx * 4 + j];
#pragma unroll
            for (int i = 0; i < 4; i++)
#pragma unroll
                for (int j = 0; j < 4; j++) acc[i][j] += pv[i] * vv[j];
        }
        __syncthreads();   // before K/V overwrite next iter
    }

    // write O = acc / l
#pragma unroll
    for (int i = 0; i < 4; i++) {
        float inv = 1.0f / l[i];
        const size_t grow = (rowbase + qb * 64 + ty * 4 + i) * DD + cbase + tx * 4;
        float4 r = make_float4(acc[i][0] * inv, acc[i][1] * inv,
                               acc[i][2] * inv, acc[i][3] * inv);
        *(float4*)(o + grow) = r;
    }
}

// ---------------------------------------------------------------------------
// Launch
// ---------------------------------------------------------------------------
static inline void run_gemm(const float* A, const float* W, const float* bias,
                            const float* res, float* C, int M, int N, int K, int gelu)
{
    dim3 grid(N / 128, M / 128);
    sgemm_kernel<<<grid, 256>>>(A, W, bias, res, C, M, N, K, gelu);
}

extern "C" void kernel_launch(void* const* d_in, const int* in_sizes, int n_in,
                              void* d_out, int out_size)
{
    const int*   tokens = (const int*)  d_in[0];
    const float* emb    = (const float*)d_in[1];
    const float* pos    = (const float*)d_in[2];
    const float* Wq     = (const float*)d_in[3];
    const float* bq     = (const float*)d_in[4];
    const float* Wk     = (const float*)d_in[5];
    const float* bk     = (const float*)d_in[6];
    const float* Wv     = (const float*)d_in[7];
    const float* bv     = (const float*)d_in[8];
    const float* Wo     = (const float*)d_in[9];
    const float* W1     = (const float*)d_in[10];
    const float* b1     = (const float*)d_in[11];
    const float* W2     = (const float*)d_in[12];
    const float* b2     = (const float*)d_in[13];
    const float* Wr     = (const float*)d_in[14];
    const float* br     = (const float*)d_in[15];
    float*       out    = (float*)d_out;

    float *x, *q, *k, *v, *o, *h, *t;
    cudaGetSymbolAddress((void**)&x, g_x);
    cudaGetSymbolAddress((void**)&q, g_q);
    cudaGetSymbolAddress((void**)&k, g_k);
    cudaGetSymbolAddress((void**)&v, g_v);
    cudaGetSymbolAddress((void**)&o, g_o);
    cudaGetSymbolAddress((void**)&h, g_h);
    cudaGetSymbolAddress((void**)&t, g_t);

    const int ASMEM = 4 * 64 * APAD * (int)sizeof(float);   // 66560 B
    cudaFuncSetAttribute(attention_kernel,
                         cudaFuncAttributeMaxDynamicSharedMemorySize, ASMEM);

    embed_kernel<<<MM, 256>>>(tokens, emb, pos, x);

    for (int l = 0; l < LL; l++) {
        const float* wq = Wq + (size_t)l * DD * DD;
        const float* wk = Wk + (size_t)l * DD * DD;
        const float* wv = Wv + (size_t)l * DD * DD;
        const float* wo = Wo + (size_t)l * DD * DD;
        const float* w1 = W1 + (size_t)l * DD * DHH;
        const float* w2 = W2 + (size_t)l * DHH * DD;
        const float* bql = bq + (size_t)l * DD;
        const float* bkl = bk + (size_t)l * DD;
        const float* bvl = bv + (size_t)l * DD;
        const float* b1l = b1 + (size_t)l * DHH;
        const float* b2l = b2 + (size_t)l * DD;

        run_gemm(x, wq, bql, nullptr, q, MM, DD, DD, 0);
        run_gemm(x, wk, bkl, nullptr, k, MM, DD, DD, 0);
        run_gemm(x, wv, bvl, nullptr, v, MM, DD, DD, 0);

        attention_kernel<<<dim3(SS / 64, BB * HH), 256, ASMEM>>>(q, k, v, o);

        // h = x + o @ Wo
        run_gemm(o, wo, nullptr, x, h, MM, DD, DD, 0);
        // t = gelu(h @ W1 + b1)
        run_gemm(h, w1, b1l, nullptr, t, MM, DHH, DD, 1);
        // x = h + t @ W2 + b2
        run_gemm(t, w2, b2l, h, x, MM, DD, DHH, 0);
    }

    // out = x @ Wr + br
    run_gemm(x, Wr, br, nullptr, out, MM, VV, DD, 0);
}

// round 3
// speedup vs baseline: 1.9968x; 1.9968x over previous
#include <cuda_runtime.h>
#include <cuda_bf16.h>
#include <math.h>
#include <stdint.h>

// ---------------------------------------------------------------------------
// Problem constants
// ---------------------------------------------------------------------------
#define BB    2
#define SSEQ  1024
#define DDIM  1024
#define HHH   16
#define DKV   64
#define DHH   4096
#define LLAY  8
#define VVOC  256
#define MM    (BB*SSEQ)        // 2048
#define NQKV  3072

// ---------------------------------------------------------------------------
// Scratch (device globals: allocation-free)
// ---------------------------------------------------------------------------
__device__ float g_x   [MM*DDIM];
__device__ float g_o   [MM*DDIM];
__device__ float g_h   [MM*DDIM];
__device__ float g_t   [MM*DHH];
__device__ float g_qkv [MM*NQKV];

__device__ float g_WqkvT[LLAY*NQKV*DDIM];
__device__ float g_WoT  [LLAY*DDIM*DDIM];
__device__ float g_W1T  [LLAY*DHH*DDIM];
__device__ float g_W2T  [LLAY*DDIM*DHH];
__device__ float g_WrT  [VVOC*DDIM];
__device__ float g_bqkv [LLAY*NQKV];

// ---------------------------------------------------------------------------
// Helpers
// ---------------------------------------------------------------------------
__device__ __forceinline__ uint32_t smem_u32(const void* p) {
    uint32_t a;
    asm("{ .reg .u64 t; cvta.to.shared.u64 t, %1; cvt.u32.u64 %0, t; }"
        : "=r"(a) : "l"(p));
    return a;
}

__device__ __forceinline__ void ldmx4(uint32_t* r, uint32_t addr) {
    asm volatile("ldmatrix.sync.aligned.m8n8.x4.shared.b16 {%0,%1,%2,%3}, [%4];"
        : "=r"(r[0]), "=r"(r[1]), "=r"(r[2]), "=r"(r[3]) : "r"(addr));
}

__device__ __forceinline__ void mma16816(float* d, const uint32_t* a,
                                         uint32_t b0, uint32_t b1) {
    asm volatile("mma.sync.aligned.m16n8k16.row.col.f32.bf16.bf16.f32 "
        "{%0,%1,%2,%3}, {%4,%5,%6,%7}, {%8,%9}, {%0,%1,%2,%3};"
        : "+f"(d[0]), "+f"(d[1]), "+f"(d[2]), "+f"(d[3])
        : "r"(a[0]), "r"(a[1]), "r"(a[2]), "r"(a[3]), "r"(b0), "r"(b1));
}

__device__ __forceinline__ float gelu_exact(float v) {
    return 0.5f * v * (1.0f + erff(v * 0.70710678118654752f));
}

__device__ __forceinline__ void split_f4(float4 v, uint2& hi, uint2& lo) {
    __nv_bfloat16 b0 = __float2bfloat16(v.x);
    __nv_bfloat16 b1 = __float2bfloat16(v.y);
    __nv_bfloat16 b2 = __float2bfloat16(v.z);
    __nv_bfloat16 b3 = __float2bfloat16(v.w);
    float r0 = v.x - __bfloat162float(b0);
    float r1 = v.y - __bfloat162float(b1);
    float r2 = v.z - __bfloat162float(b2);
    float r3 = v.w - __bfloat162float(b3);
    hi.x = ((uint32_t)__bfloat16_as_ushort(b1) << 16) | __bfloat16_as_ushort(b0);
    hi.y = ((uint32_t)__bfloat16_as_ushort(b3) << 16) | __bfloat16_as_ushort(b2);
    __nv_bfloat162 l01 = __floats2bfloat162_rn(r0, r1);
    __nv_bfloat162 l23 = __floats2bfloat162_rn(r2, r3);
    lo.x = *(uint32_t*)&l01;
    lo.y = *(uint32_t*)&l23;
}

// ---------------------------------------------------------------------------
// GEMM: C[M,N] = act(A[M,K] @ Bt^T + bias) + res ;  Bt is [N,K]
// bf16x3 split precision via mma.sync m16n8k16. 128x128 tile, BK=32,
// 8 warps (2x4), warp tile 64x32, double-buffered SMEM.
// ---------------------------------------------------------------------------
#define LDB        80                 // smem row stride in bytes (40 bf16)
#define TILE_B     (128*LDB)          // 10240
#define OFF_AHI    0
#define OFF_ALO    (1*TILE_B)
#define OFF_BHI    (2*TILE_B)
#define OFF_BLO    (3*TILE_B)
#define STAGE_B    (4*TILE_B)         // 40960
#define GSMEM      (2*STAGE_B)        // 81920

__global__ void __launch_bounds__(256)
gemm_mma(const float* __restrict__ A, const float* __restrict__ Bt,
         const float* __restrict__ bias, const float* __restrict__ res,
         float* __restrict__ C, int M, int N, int K, int gelu)
{
    extern __shared__ char sm[];
    const uint32_t smb = smem_u32(sm);

    const int tid  = threadIdx.x;
    const int lane = tid & 31;
    const int wid  = tid >> 5;
    const int wr   = wid >> 2;          // 0..1
    const int wc   = wid & 3;           // 0..3
    const int m0   = blockIdx.y * 128;
    const int n0   = blockIdx.x * 128;

    // staging: thread -> (row = (tid>>3)+p*32, c4 = tid&7), p = 0..3
    const int sc4  = tid & 7;
    const int srow = tid >> 3;
    const float* aP = A  + (size_t)(m0 + srow) * K + sc4 * 4;
    const float* bP = Bt + (size_t)(n0 + srow) * K + sc4 * 4;

    float acc[4][4][4];
#pragma unroll
    for (int i = 0; i < 4; i++)
#pragma unroll
        for (int j = 0; j < 4; j++)
#pragma unroll
            for (int q = 0; q < 4; q++) acc[i][j][q] = 0.0f;

    float4 ra[4], rb[4];
    // preload tile 0
#pragma unroll
    for (int p = 0; p < 4; p++) {
        ra[p] = __ldg((const float4*)(aP + (size_t)p * 32 * K));
        rb[p] = __ldg((const float4*)(bP + (size_t)p * 32 * K));
    }
    {
        char* sp = sm;   // stage 0
#pragma unroll
        for (int p = 0; p < 4; p++) {
            uint32_t off = (uint32_t)((srow + p * 32) * LDB + sc4 * 8);
            uint2 hi, lo;
            split_f4(ra[p], hi, lo);
            *(uint2*)(sp + OFF_AHI + off) = hi;
            *(uint2*)(sp + OFF_ALO + off) = lo;
            split_f4(rb[p], hi, lo);
            *(uint2*)(sp + OFF_BHI + off) = hi;
            *(uint2*)(sp + OFF_BLO + off) = lo;
        }
    }
    __syncthreads();

    const int nIt = K >> 5;
    for (int it = 0; it < nIt; ++it) {
        const int cur = it & 1;

        if (it + 1 < nIt) {
#pragma unroll
            for (int p = 0; p < 4; p++) {
                ra[p] = __ldg((const float4*)(aP + (it + 1) * 32 + (size_t)p * 32 * K));
                rb[p] = __ldg((const float4*)(bP + (it + 1) * 32 + (size_t)p * 32 * K));
            }
        }

        // ---- compute on stage cur ----
        const uint32_t stage = smb + cur * STAGE_B;
        const uint32_t aHiB = stage + OFF_AHI + (uint32_t)((wr * 64 + (lane & 15)) * LDB + (lane >> 4) * 16);
        const uint32_t aLoB = aHiB + TILE_B;
        const uint32_t bHiB = stage + OFF_BHI + (uint32_t)((wc * 32 + lane) * LDB);
        const uint32_t bLoB = bHiB + TILE_B;

#pragma unroll
        for (int kc = 0; kc < 2; kc++) {
            uint32_t ahi[4][4], alo[4][4];
            uint32_t bh0[4], bh1[4], bl0[4], bl1[4];
#pragma unroll
            for (int mt = 0; mt < 4; mt++) {
                ldmx4(ahi[mt], aHiB + mt * 16 * LDB + kc * 32);
                ldmx4(alo[mt], aLoB + mt * 16 * LDB + kc * 32);
            }
            ldmx4(bh0, bHiB + kc * 32);
            ldmx4(bh1, bHiB + kc * 32 + 16);
            ldmx4(bl0, bLoB + kc * 32);
            ldmx4(bl1, bLoB + kc * 32 + 16);

#pragma unroll
            for (int mt = 0; mt < 4; mt++)
#pragma unroll
                for (int nt = 0; nt < 4; nt++) {
                    mma16816(acc[mt][nt], ahi[mt], bh0[nt], bh1[nt]);
                    mma16816(acc[mt][nt], ahi[mt], bl0[nt], bl1[nt]);
                    mma16816(acc[mt][nt], alo[mt], bh0[nt], bh1[nt]);
                }
        }

        // ---- stage (it+1) store ----
        if (it + 1 < nIt) {
            char* sp = sm + ((it + 1) & 1) * STAGE_B;
#pragma unroll
            for (int p = 0; p < 4; p++) {
                uint32_t off = (uint32_t)((srow + p * 32) * LDB + sc4 * 8);
                uint2 hi, lo;
                split_f4(ra[p], hi, lo);
                *(uint2*)(sp + OFF_AHI + off) = hi;
                *(uint2*)(sp + OFF_ALO + off) = lo;
                split_f4(rb[p], hi, lo);
                *(uint2*)(sp + OFF_BHI + off) = hi;
                *(uint2*)(sp + OFF_BLO + off) = lo;
            }
        }
        __syncthreads();
    }

    // ---- epilogue: fused bias / gelu / residual ----
    const int er = m0 + wr * 64 + (lane >> 2);
    const int ec = n0 + wc * 32 + (lane & 3) * 2;
#pragma unroll
    for (int mt = 0; mt < 4; mt++) {
#pragma unroll
        for (int half = 0; half < 2; half++) {
            const int row = er + mt * 16 + half * 8;
            float* crow = C + (size_t)row * N;
            const float* rrow = res ? res + (size_t)row * N : nullptr;
#pragma unroll
            for (int nt = 0; nt < 4; nt++) {
                const int col = ec + nt * 8;
                float v0 = acc[mt][nt][half * 2 + 0];
                float v1 = acc[mt][nt][half * 2 + 1];
                if (bias) { v0 += bias[col]; v1 += bias[col + 1]; }
                if (gelu) { v0 = gelu_exact(v0); v1 = gelu_exact(v1); }
                if (rrow) { v0 += rrow[col]; v1 += rrow[col + 1]; }
                *(float2*)(crow + col) = make_float2(v0, v1);
            }
        }
    }
}

// ---------------------------------------------------------------------------
// Transpose src[K,N] -> dst[N,K] (32x32 tiles)
// ---------------------------------------------------------------------------
__global__ void transpose32(const float* __restrict__ src, float* __restrict__ dst,
                            int K, int N)
{
    __shared__ float t[32][33];
    const int k0 = blockIdx.y * 32, n0 = blockIdx.x * 32;
    const int tx = threadIdx.x, ty = threadIdx.y;   // (32, 8)
#pragma unroll
    for (int i = 0; i < 32; i += 8)
        t[ty + i][tx] = src[(size_t)(k0 + ty + i) * N + n0 + tx];
    __syncthreads();
#pragma unroll
    for (int i = 0; i < 32; i += 8)
        dst[(size_t)(n0 + ty + i) * K + k0 + tx] = t[tx][ty + i];
}

__global__ void bias_concat(const float* __restrict__ bq, const float* __restrict__ bk,
                            const float* __restrict__ bv, float* __restrict__ dst)
{
    int l = blockIdx.y;
    int i = blockIdx.x * 256 + threadIdx.x;
    dst[l*NQKV + i]        = bq[l*DDIM + i];
    dst[l*NQKV + 1024 + i] = bk[l*DDIM + i];
    dst[l*NQKV + 2048 + i] = bv[l*DDIM + i];
}

// ---------------------------------------------------------------------------
// Embedding
// ---------------------------------------------------------------------------
__global__ void embed_kernel(const int* __restrict__ tokens,
                             const float* __restrict__ emb,
                             const float* __restrict__ pos,
                             float* __restrict__ x)
{
    int i = blockIdx.x;
    int s = i & (SSEQ - 1);
    int t = tokens[i];
    const float4* e4 = (const float4*)(emb + (size_t)t * DDIM);
    const float4* p4 = (const float4*)(pos + (size_t)s * DDIM);
    float4*       x4 = (float4*)(x + (size_t)i * DDIM);
    int d = threadIdx.x;
    float4 a = e4[d], b = p4[d];
    x4[d] = make_float4(a.x + b.x, a.y + b.y, a.z + b.z, a.w + b.w);
}

// ---------------------------------------------------------------------------
// Flash attention (causal), qkv packed [M, 3072]
// ---------------------------------------------------------------------------
#define APAD 65
__global__ void __launch_bounds__(256)
attention_kernel(const float* __restrict__ qkv, float* __restrict__ o)
{
    extern __shared__ float smf[];
    float* Qs = smf;
    float* Ks = Qs + 64 * APAD;
    float* Vs = Ks + 64 * APAD;
    float* Ps = Vs + 64 * APAD;

    const int tid = threadIdx.x;
    const int qb  = blockIdx.x;
    const int bh  = blockIdx.y;
    const int b   = bh >> 4;
    const int h   = bh & 15;
    const size_t rowbase = (size_t)b * SSEQ;
    const int qc = h * DKV, kc = 1024 + h * DKV, vc = 2048 + h * DKV;

    const int ty = tid >> 4;
    const int tx = tid & 15;
    const float scale = 0.125f;

    for (int it = tid; it < 64 * 16; it += 256) {
        int rr = it >> 4, c4 = (it & 15) * 4;
        float4 a = *(const float4*)(qkv + (rowbase + qb*64 + rr) * NQKV + qc + c4);
        Qs[rr*APAD + c4+0] = a.x; Qs[rr*APAD + c4+1] = a.y;
        Qs[rr*APAD + c4+2] = a.z; Qs[rr*APAD + c4+3] = a.w;
    }

    float m[4], l[4], acc[4][4];
#pragma unroll
    for (int i = 0; i < 4; i++) {
        m[i] = -INFINITY; l[i] = 0.0f;
#pragma unroll
        for (int j = 0; j < 4; j++) acc[i][j] = 0.0f;
    }
    __syncthreads();

    for (int jt = 0; jt <= qb; jt++) {
        for (int it = tid; it < 64 * 16; it += 256) {
            int rr = it >> 4, c4 = (it & 15) * 4;
            const size_t grow = (rowbase + jt*64 + rr) * NQKV;
            float4 a = *(const float4*)(qkv + grow + kc + c4);
            Ks[rr*APAD + c4+0] = a.x; Ks[rr*APAD + c4+1] = a.y;
            Ks[rr*APAD + c4+2] = a.z; Ks[rr*APAD + c4+3] = a.w;
            float4 c = *(const float4*)(qkv + grow + vc + c4);
            Vs[rr*APAD + c4+0] = c.x; Vs[rr*APAD + c4+1] = c.y;
            Vs[rr*APAD + c4+2] = c.z; Vs[rr*APAD + c4+3] = c.w;
        }
        __syncthreads();

        float s[4][4];
#pragma unroll
        for (int i = 0; i < 4; i++)
#pragma unroll
            for (int j = 0; j < 4; j++) s[i][j] = 0.0f;
#pragma unroll 8
        for (int kk = 0; kk < 64; kk++) {
            float qv[4], kv[4];
#pragma unroll
            for (int i = 0; i < 4; i++) qv[i] = Qs[(ty*4+i)*APAD + kk];
#pragma unroll
            for (int j = 0; j < 4; j++) kv[j] = Ks[(tx*4+j)*APAD + kk];
#pragma unroll
            for (int i = 0; i < 4; i++)
#pragma unroll
                for (int j = 0; j < 4; j++) s[i][j] += qv[i] * kv[j];
        }

#pragma unroll
        for (int i = 0; i < 4; i++) {
            int qrow = qb*64 + ty*4 + i;
#pragma unroll
            for (int j = 0; j < 4; j++) {
                int kcol = jt*64 + tx*4 + j;
                s[i][j] = (kcol > qrow) ? -INFINITY : s[i][j] * scale;
            }
        }

#pragma unroll
        for (int i = 0; i < 4; i++) {
            float rm = fmaxf(fmaxf(s[i][0], s[i][1]), fmaxf(s[i][2], s[i][3]));
#pragma unroll
            for (int off = 1; off < 16; off <<= 1)
                rm = fmaxf(rm, __shfl_xor_sync(0xffffffffu, rm, off));
            float mnew = fmaxf(m[i], rm);
            float corr = expf(m[i] - mnew);
            l[i] *= corr;
#pragma unroll
            for (int j = 0; j < 4; j++) acc[i][j] *= corr;
            float rs = 0.0f;
#pragma unroll
            for (int j = 0; j < 4; j++) {
                float p = expf(s[i][j] - mnew);
                s[i][j] = p; rs += p;
            }
#pragma unroll
            for (int off = 1; off < 16; off <<= 1)
                rs += __shfl_xor_sync(0xffffffffu, rs, off);
            l[i] += rs; m[i] = mnew;
        }

#pragma unroll
        for (int i = 0; i < 4; i++)
#pragma unroll
            for (int j = 0; j < 4; j++)
                Ps[(ty*4+i)*APAD + tx*4 + j] = s[i][j];
        __syncthreads();

#pragma unroll 8
        for (int kk = 0; kk < 64; kk++) {
            float pv[4], vv[4];
#pragma unroll
            for (int i = 0; i < 4; i++) pv[i] = Ps[(ty*4+i)*APAD + kk];
#pragma unroll
            for (int j = 0; j < 4; j++) vv[j] = Vs[kk*APAD + tx*4 + j];
#pragma unroll
            for (int i = 0; i < 4; i++)
#pragma unroll
                for (int j = 0; j < 4; j++) acc[i][j] += pv[i] * vv[j];
        }
        __syncthreads();
    }

#pragma unroll
    for (int i = 0; i < 4; i++) {
        float inv = 1.0f / l[i];
        const size_t grow = (rowbase + qb*64 + ty*4 + i) * DDIM + h*DKV + tx*4;
        *(float4*)(o + grow) = make_float4(acc[i][0]*inv, acc[i][1]*inv,
                                           acc[i][2]*inv, acc[i][3]*inv);
    }
}

// ---------------------------------------------------------------------------
// Host
// ---------------------------------------------------------------------------
static inline void run_gemm(const float* A, const float* Bt, const float* bias,
                            const float* res, float* C, int M, int N, int K, int gelu)
{
    dim3 grid(N / 128, M / 128);
    gemm_mma<<<grid, 256, GSMEM>>>(A, Bt, bias, res, C, M, N, K, gelu);
}

static inline void tr(const float* s, float* d, int K, int N)
{
    transpose32<<<dim3(N / 32, K / 32), dim3(32, 8)>>>(s, d, K, N);
}

extern "C" void kernel_launch(void* const* d_in, const int* in_sizes, int n_in,
                              void* d_out, int out_size)
{
    const int*   tokens = (const int*)  d_in[0];
    const float* emb    = (const float*)d_in[1];
    const float* pos    = (const float*)d_in[2];
    const float* Wq     = (const float*)d_in[3];
    const float* bq     = (const float*)d_in[4];
    const float* Wk     = (const float*)d_in[5];
    const float* bk     = (const float*)d_in[6];
    const float* Wv     = (const float*)d_in[7];
    const float* bv     = (const float*)d_in[8];
    const float* Wo     = (const float*)d_in[9];
    const float* W1     = (const float*)d_in[10];
    const float* b1     = (const float*)d_in[11];
    const float* W2     = (const float*)d_in[12];
    const float* b2     = (const float*)d_in[13];
    const float* Wr     = (const float*)d_in[14];
    const float* br     = (const float*)d_in[15];
    float*       out    = (float*)d_out;

    float *x, *o, *h, *t, *qkv, *WqkvT, *WoT, *W1T, *W2T, *WrT, *bqkv;
    cudaGetSymbolAddress((void**)&x,     g_x);
    cudaGetSymbolAddress((void**)&o,     g_o);
    cudaGetSymbolAddress((void**)&h,     g_h);
    cudaGetSymbolAddress((void**)&t,     g_t);
    cudaGetSymbolAddress((void**)&qkv,   g_qkv);
    cudaGetSymbolAddress((void**)&WqkvT, g_WqkvT);
    cudaGetSymbolAddress((void**)&WoT,   g_WoT);
    cudaGetSymbolAddress((void**)&W1T,   g_W1T);
    cudaGetSymbolAddress((void**)&W2T,   g_W2T);
    cudaGetSymbolAddress((void**)&WrT,   g_WrT);
    cudaGetSymbolAddress((void**)&bqkv,  g_bqkv);

    cudaFuncSetAttribute(gemm_mma,
                         cudaFuncAttributeMaxDynamicSharedMemorySize, GSMEM);
    const int ASMEM = 4 * 64 * APAD * (int)sizeof(float);
    cudaFuncSetAttribute(attention_kernel,
                         cudaFuncAttributeMaxDynamicSharedMemorySize, ASMEM);

    // weight transposes (once per call)
    for (int l = 0; l < LLAY; l++) {
        tr(Wq + (size_t)l*DDIM*DDIM, WqkvT + (size_t)l*NQKV*DDIM + 0*DDIM*DDIM, DDIM, DDIM);
        tr(Wk + (size_t)l*DDIM*DDIM, WqkvT + (size_t)l*NQKV*DDIM + 1*DDIM*DDIM, DDIM, DDIM);
        tr(Wv + (size_t)l*DDIM*DDIM, WqkvT + (size_t)l*NQKV*DDIM + 2*DDIM*DDIM, DDIM, DDIM);
        tr(Wo + (size_t)l*DDIM*DDIM, WoT   + (size_t)l*DDIM*DDIM, DDIM, DDIM);
        tr(W1 + (size_t)l*DDIM*DHH,  W1T   + (size_t)l*DHH*DDIM,  DDIM, DHH);
        tr(W2 + (size_t)l*DHH*DDIM,  W2T   + (size_t)l*DDIM*DHH,  DHH,  DDIM);
    }
    tr(Wr, WrT, DDIM, VVOC);
    bias_concat<<<dim3(4, LLAY), 256>>>(bq, bk, bv, bqkv);

    embed_kernel<<<MM, 256>>>(tokens, emb, pos, x);

    for (int l = 0; l < LLAY; l++) {
        const float* wqkvT = WqkvT + (size_t)l*NQKV*DDIM;
        const float* woT   = WoT   + (size_t)l*DDIM*DDIM;
        const float* w1T   = W1T   + (size_t)l*DHH*DDIM;
        const float* w2T   = W2T   + (size_t)l*DDIM*DHH;

        run_gemm(x, wqkvT, bqkv + (size_t)l*NQKV, nullptr, qkv, MM, NQKV, DDIM, 0);
        attention_kernel<<<dim3(SSEQ/64, BB*HHH), 256, ASMEM>>>(qkv, o);
        run_gemm(o, woT, nullptr, x, h, MM, DDIM, DDIM, 0);
        run_gemm(h, w1T, b1 + (size_t)l*DHH, nullptr, t, MM, DHH, DDIM, 1);
        run_gemm(t, w2T, b2 + (size_t)l*DDIM, h, x, MM, DDIM, DHH, 0);
    }

    run_gemm(x, WrT, br, nullptr, out, MM, VVOC, DDIM, 0);
}